// round 17
// baseline (speedup 1.0000x reference)
#include <cuda_runtime.h>
#include <cuda_fp16.h>
#include <cstdint>

#define N_NODES 100000
#define N_EDGES 625000
#define D_IN    128
#define D_HID   256
#define NSCAN   100352        // 392 * 256 >= N_NODES + 1
#define NBLK    392
#define NTILES  1563          // ceil(100000/64)

// ---------------------------------------------------------------------------
// Scratch (__device__ globals; allocation-free rule)
// ---------------------------------------------------------------------------
__device__ int    g_off[NSCAN];        // CSR offsets (exclusive prefix)
__device__ int    g_bsum[NBLK];        // scan block totals
__device__ int    g_cur[N_NODES];      // scatter cursors
__device__ int    g_csr[N_EDGES];      // CSR adjacency (src per slot)
__device__ __half g_aggh[(size_t)N_NODES * D_IN];   // mean-aggregated, fp16
__device__ __half g_xh[(size_t)N_NODES * D_IN];     // x converted to fp16
__device__ __half g_Wh[256 * 256];     // W_cat^T: [n][k] fp16 (512B rows)
__device__ float  g_part[(size_t)N_NODES * 16];     // head partials (13 used)

// ---------------------------------------------------------------------------
// Kernel I: fused init — xconv (0..12499), prep (12500..12597),
// wconv (12598..12853), zero g_part (12854..14416)
// ---------------------------------------------------------------------------
__global__ void init_kernel(const float* __restrict__ x,
                            const float* __restrict__ wl,
                            const float* __restrict__ wr) {
    int b = blockIdx.x;
    int tid = threadIdx.x;
    if (b < 12500) {                       // xconv: 3,200,000 float4
        int i = b * 256 + tid;
        float4 v = ((const float4*)x)[i];
        __half2 h01 = __floats2half2_rn(v.x, v.y);
        __half2 h23 = __floats2half2_rn(v.z, v.w);
        uint2 u;
        u.x = *reinterpret_cast<uint32_t*>(&h01);
        u.y = *reinterpret_cast<uint32_t*>(&h23);
        ((uint2*)g_xh)[i] = u;
    } else if (b < 12598) {                // prep: zero g_off (25,088 int4)
        int i = (b - 12500) * 256 + tid;
        ((int4*)g_off)[i] = make_int4(0, 0, 0, 0);
    } else if (b < 12854) {                // wconv: 65,536 elems
        int idx = (b - 12598) * 256 + tid;
        int n = idx >> 8;
        int k = idx & 255;
        float v = (k < 128) ? wl[k * 256 + n] : wr[(k - 128) * 256 + n];
        g_Wh[idx] = __float2half_rn(v);
    } else {                               // zero g_part: 400,000 float4
        int i = (b - 12854) * 256 + tid;
        if (i < N_NODES * 4)
            ((float4*)g_part)[i] = make_float4(0.f, 0.f, 0.f, 0.f);
    }
}

// ---------------------------------------------------------------------------
// CSR build chain (unchanged)
// ---------------------------------------------------------------------------
__global__ void hist_kernel(const int* __restrict__ ei) {
    int e = blockIdx.x * blockDim.x + threadIdx.x;
    if (e < N_EDGES)
        atomicAdd(&g_off[ei[N_EDGES + e] + 1], 1);
}

__global__ void scan_block_kernel() {
    __shared__ int s[256];
    int tid = threadIdx.x;
    int i = blockIdx.x * 256 + tid;
    s[tid] = g_off[i];
#pragma unroll
    for (int off = 1; off < 256; off <<= 1) {
        __syncthreads();
        int tmp = (tid >= off) ? s[tid - off] : 0;
        __syncthreads();
        s[tid] += tmp;
    }
    __syncthreads();
    g_off[i] = s[tid];
    if (tid == 255) g_bsum[blockIdx.x] = s[255];
}

__global__ void scan_add_kernel() {
    __shared__ int ssum[256];
    int tid = threadIdx.x;
    int b = blockIdx.x;

    int v = 0;
    for (int j = tid; j < b; j += 256) v += g_bsum[j];
    ssum[tid] = v;
#pragma unroll
    for (int off = 128; off > 0; off >>= 1) {
        __syncthreads();
        if (tid < off) ssum[tid] += ssum[tid + off];
    }
    __syncthreads();
    int add = ssum[0];

    int i = b * 256 + tid;
    int val = g_off[i] + add;
    g_off[i] = val;
    if (i < N_NODES) g_cur[i] = val;
}

__global__ void scatter_kernel(const int* __restrict__ ei) {
    int e = blockIdx.x * blockDim.x + threadIdx.x;
    if (e < N_EDGES) {
        int src = ei[e];
        int dst = ei[N_EDGES + e];
        int idx = atomicAdd(&g_cur[dst], 1);
        g_csr[idx] = src;
    }
}

// ---------------------------------------------------------------------------
// Kernel P4: gather-aggregate (warp per node), cooperative index fetch
// ---------------------------------------------------------------------------
__global__ void gather_kernel() {
    int n    = blockIdx.x * 8 + (threadIdx.x >> 5);
    int lane = threadIdx.x & 31;

    int beg = g_off[n], end = g_off[n + 1];
    int d = end - beg;
    float a0 = 0.f, a1 = 0.f, a2 = 0.f, a3 = 0.f;

    for (int b0 = 0; b0 < d; b0 += 32) {
        int cnt = min(32, d - b0);
        int idx = (lane < cnt) ? g_csr[beg + b0 + lane] : 0;
#pragma unroll 4
        for (int j = 0; j < cnt; j++) {
            int s = __shfl_sync(0xffffffff, idx, j);
            uint2 u = *(const uint2*)(g_xh + (long long)s * D_IN + lane * 4);
            __half2 h01 = *reinterpret_cast<__half2*>(&u.x);
            __half2 h23 = *reinterpret_cast<__half2*>(&u.y);
            float2 f01 = __half22float2(h01);
            float2 f23 = __half22float2(h23);
            a0 += f01.x; a1 += f01.y; a2 += f23.x; a3 += f23.y;
        }
    }
    float inv = (d > 0) ? 1.f / (float)d : 0.f;
    __half2 h01 = __floats2half2_rn(a0 * inv, a1 * inv);
    __half2 h23 = __floats2half2_rn(a2 * inv, a3 * inv);
    uint2 u;
    u.x = *reinterpret_cast<uint32_t*>(&h01);
    u.y = *reinterpret_cast<uint32_t*>(&h23);
    *(uint2*)(g_aggh + (long long)n * D_IN + lane * 4) = u;
}

// ---------------------------------------------------------------------------
// PTX helpers
// ---------------------------------------------------------------------------
__device__ __forceinline__ uint32_t smem_u32(const void* p) {
    uint32_t a;
    asm("{ .reg .u64 t; cvta.to.shared.u64 t, %1; cvt.u32.u64 %0, t; }"
        : "=r"(a) : "l"(p));
    return a;
}
__device__ __forceinline__ void mma_f16(float* d, const uint32_t* a,
                                        uint32_t b0, uint32_t b1) {
    asm volatile(
        "mma.sync.aligned.m16n8k16.row.col.f32.f16.f16.f32 "
        "{%0,%1,%2,%3}, {%4,%5,%6,%7}, {%8,%9}, {%0,%1,%2,%3};"
        : "+f"(d[0]), "+f"(d[1]), "+f"(d[2]), "+f"(d[3])
        : "r"(a[0]), "r"(a[1]), "r"(a[2]), "r"(a[3]), "r"(b0), "r"(b1));
}
#define LDSM4(d0, d1, d2, d3, addr) \
    asm volatile("ldmatrix.sync.aligned.m8n8.x4.shared.b16 {%0,%1,%2,%3}, [%4];" \
        : "=r"(d0), "=r"(d1), "=r"(d2), "=r"(d3) : "r"(addr))
#define CPASYNC16(dst, src) \
    asm volatile("cp.async.ca.shared.global [%0], [%1], 16;" :: "r"(dst), "l"(src))
#define CPCOMMIT() asm volatile("cp.async.commit_group;" ::: "memory")
#define CPWAIT0()  asm volatile("cp.async.wait_group 0;" ::: "memory")

// ---------------------------------------------------------------------------
// Kernel N: persistent B-stationary fp16 mma.sync node kernel.
// grid = 296 (2 CTAs/SM). CTA owns N-half = 128 cols (nhalf = bid & 1),
// stages its B half ONCE (all K), then loops over node tiles (64 nodes,
// tile = bid>>1, stride 148). Warp tile M32 x N32 (acc = 32 regs).
// Per tile: A staged in 4 k-chunks (double-buffered cp.async), MMAs,
// head partials flushed to g_part via RED.
//
// SMEM/CTA (~101.5 KB -> 2 CTAs/SM):
//   A bufs [2 buf][64 rows][72 halfs]          @ 0       (18,432)
//   B [4 kc][128 rows][72 halfs]               @ 18,432  (73,728)
//   s_wh [128 local cols][17] f32              @ 92,160  (8,704)
//   s_bl [128] f32                             @ 100,864 (512)
// ---------------------------------------------------------------------------
#define AST     144           // bytes per smem row (64 halfs + 16B pad)
#define A_IMG   9216          // 64*144
#define B_OFF   18432
#define BCH     18432         // per k-chunk: 128 rows * 144
#define OFF_WH  92160
#define OFF_BL  100864
#define SMEM_DYN 101376

__global__ __launch_bounds__(256, 2) void node_mma_kernel(
    const float* __restrict__ wp,
    const float* __restrict__ ws,
    const float* __restrict__ bl)
{
    extern __shared__ float4 smem4[];
    char* smem = (char*)smem4;
    const uint32_t sb = smem_u32(smem);
    float* s_wh = (float*)(smem + OFF_WH);
    float* s_bl = (float*)(smem + OFF_BL);

    const int t    = threadIdx.x;
    const int w    = t >> 5;
    const int lane = t & 31;
    const int lq   = lane >> 2;
    const int lr   = (lane & 3) * 2;

    const int nhalf = blockIdx.x & 1;       // which 128-col half
    const int ncol0 = nhalf * 128;          // global col base

    // ---- one-time: stage full B half (all 4 k-chunks) + heads + bl ----
    {
        const char* gs = (const char*)&g_Wh[0];
#pragma unroll
        for (int c = 0; c < 4; c++) {
#pragma unroll
            for (int it = 0; it < 4; it++) {
                int i = t + it * 256;       // 0..1023
                int n = i >> 3, q = i & 7;  // n: local row 0..127
                uint32_t dst = sb + B_OFF + c * BCH + n * AST + q * 16;
                CPASYNC16(dst, gs + (ncol0 + n) * 512 + c * 128 + q * 16);
            }
        }
        CPCOMMIT();
        // head weights for our cols (local col j, 13 rows) + bias
        for (int i = t; i < 13 * 128; i += 256) {
            int j = i & 127, cc = i >> 7;
            int gj = ncol0 + j;
            s_wh[j * 17 + cc] = (cc < 7) ? wp[gj * 7 + cc] : ws[gj * 6 + (cc - 7)];
        }
        if (t < 128) s_bl[t] = bl[ncol0 + t];
        CPWAIT0();
        __syncthreads();
    }

    const int m0  = (w & 1) * 32;           // 2 M-strips
    const int nbl = (w >> 1) * 32;          // 4 local N-strips (32 each)

    const int tt    = lane >> 3;
    const int arow  = ((tt & 1) * 8) + (lane & 7);
    const int acol2 = ((tt >> 1) * 8) * 2;

    // ---- persistent tile loop ----
    for (int tile = blockIdx.x >> 1; tile < NTILES; tile += 148) {
        const long long base = (long long)tile * 64;

        float acc[32];
#pragma unroll
        for (int i = 0; i < 32; i++) acc[i] = 0.f;

        // stage A chunk helper
        auto stageA = [&](int c, int buf) {
            const __half* gsrc = (c < 2) ? g_aggh : g_xh;
            int koff = (c & 1) * 64;
#pragma unroll
            for (int it = 0; it < 2; it++) {
                int i = t + it * 256;
                int m = i >> 3, q = i & 7;
                long long node = base + m;
                if (node >= N_NODES) node = N_NODES - 1;
                uint32_t dst = sb + buf * A_IMG + m * AST + q * 16;
                CPASYNC16(dst, (const char*)(gsrc + node * D_IN + koff) + q * 16);
            }
        };

        stageA(0, 0);
        CPCOMMIT();
        CPWAIT0();
        __syncthreads();

        for (int c = 0; c < 4; c++) {
            int cur = c & 1, nxt = cur ^ 1;
            if (c < 3) { stageA(c + 1, nxt); CPCOMMIT(); }

            const uint32_t Ab = sb + cur * A_IMG;
            const uint32_t Bb = sb + B_OFF + c * BCH;
#pragma unroll
            for (int ks = 0; ks < 4; ks++) {
                int kb = ks * 32;
                uint32_t a0[4], a1[4], b[2][4];
                uint32_t ad = Ab + (m0 + arow) * AST + kb + acol2;
                LDSM4(a0[0], a0[1], a0[2], a0[3], ad);
                LDSM4(a1[0], a1[1], a1[2], a1[3], ad + 16 * AST);
#pragma unroll
                for (int j = 0; j < 2; j++) {
                    uint32_t bd = Bb + (nbl + j * 16 + arow) * AST + kb + acol2;
                    LDSM4(b[j][0], b[j][1], b[j][2], b[j][3], bd);
                }
#pragma unroll
                for (int j = 0; j < 2; j++) {
                    int nt0 = j * 2, nt1 = j * 2 + 1;
                    mma_f16(acc + nt0 * 4,      a0, b[j][0], b[j][2]);
                    mma_f16(acc + nt1 * 4,      a0, b[j][1], b[j][3]);
                    mma_f16(acc + 16 + nt0 * 4, a1, b[j][0], b[j][2]);
                    mma_f16(acc + 16 + nt1 * 4, a1, b[j][1], b[j][3]);
                }
            }
            if (c < 3) CPWAIT0();
            __syncthreads();
        }

        // ---- per-tile epilogue: relu + head partials -> RED to g_part ----
#pragma unroll
        for (int mi = 0; mi < 2; mi++) {
            float pr0[13], pr1[13];
#pragma unroll
            for (int cc = 0; cc < 13; cc++) { pr0[cc] = 0.f; pr1[cc] = 0.f; }
#pragma unroll
            for (int nt = 0; nt < 4; nt++) {
                int lc = nbl + nt * 8 + lr;        // local col
                float b0 = s_bl[lc], b1 = s_bl[lc + 1];
                const float* d = acc + mi * 16 + nt * 4;
                float h00 = fmaxf(d[0] + b0, 0.f), h01 = fmaxf(d[1] + b1, 0.f);
                float h10 = fmaxf(d[2] + b0, 0.f), h11 = fmaxf(d[3] + b1, 0.f);
                const float* w0 = s_wh + lc * 17;
                const float* w1 = w0 + 17;
#pragma unroll
                for (int cc = 0; cc < 13; cc++) {
                    float wa = w0[cc], wb = w1[cc];
                    pr0[cc] = fmaf(h00, wa, fmaf(h01, wb, pr0[cc]));
                    pr1[cc] = fmaf(h10, wa, fmaf(h11, wb, pr1[cc]));
                }
            }
#pragma unroll
            for (int cc = 0; cc < 13; cc++) {
                pr0[cc] += __shfl_xor_sync(0xffffffff, pr0[cc], 1);
                pr0[cc] += __shfl_xor_sync(0xffffffff, pr0[cc], 2);
                pr1[cc] += __shfl_xor_sync(0xffffffff, pr1[cc], 1);
                pr1[cc] += __shfl_xor_sync(0xffffffff, pr1[cc], 2);
            }
            if ((lane & 3) == 0) {
                int r = m0 + mi * 16 + lq;
                long long n0 = base + r;
                long long n1 = base + r + 8;
                if (n0 < N_NODES) {
#pragma unroll
                    for (int cc = 0; cc < 13; cc++)
                        atomicAdd(&g_part[n0 * 16 + cc], pr0[cc]);
                }
                if (n1 < N_NODES) {
#pragma unroll
                    for (int cc = 0; cc < 13; cc++)
                        atomicAdd(&g_part[n1 * 16 + cc], pr1[cc]);
                }
            }
        }
        __syncthreads();   // acc/epilogue done; safe to restage A next tile
    }
}

// ---------------------------------------------------------------------------
// Kernel F: finish — biases + log_softmax + writeout (1 thread per node)
// ---------------------------------------------------------------------------
__global__ void finish_kernel(const float* __restrict__ bp,
                              const float* __restrict__ bs,
                              float* __restrict__ out) {
    int n = blockIdx.x * 256 + threadIdx.x;
    if (n >= N_NODES) return;
    float o[13];
    float4 p0 = ((const float4*)(g_part + (long long)n * 16))[0];
    float4 p1 = ((const float4*)(g_part + (long long)n * 16))[1];
    float4 p2 = ((const float4*)(g_part + (long long)n * 16))[2];
    float4 p3 = ((const float4*)(g_part + (long long)n * 16))[3];
    o[0] = p0.x; o[1] = p0.y; o[2] = p0.z; o[3] = p0.w;
    o[4] = p1.x; o[5] = p1.y; o[6] = p1.z; o[7] = p1.w;
    o[8] = p2.x; o[9] = p2.y; o[10] = p2.z; o[11] = p2.w;
    o[12] = p3.x;
#pragma unroll
    for (int cc = 0; cc < 7; cc++) o[cc] += bp[cc];
#pragma unroll
    for (int cc = 7; cc < 13; cc++) o[cc] += bs[cc - 7];

    float mx = o[0];
#pragma unroll
    for (int cc = 1; cc < 7; cc++) mx = fmaxf(mx, o[cc]);
    float s = 0.f;
#pragma unroll
    for (int cc = 0; cc < 7; cc++) s += __expf(o[cc] - mx);
    float lse = mx + __logf(s);
#pragma unroll
    for (int cc = 0; cc < 7; cc++) out[(long long)n * 7 + cc] = o[cc] - lse;

    mx = o[7];
#pragma unroll
    for (int cc = 8; cc < 13; cc++) mx = fmaxf(mx, o[cc]);
    s = 0.f;
#pragma unroll
    for (int cc = 7; cc < 13; cc++) s += __expf(o[cc] - mx);
    lse = mx + __logf(s);
    float* out2 = out + (long long)N_NODES * 7;
#pragma unroll
    for (int cc = 0; cc < 6; cc++) out2[(long long)n * 6 + cc] = o[7 + cc] - lse;
}

// ---------------------------------------------------------------------------
extern "C" void kernel_launch(void* const* d_in, const int* in_sizes, int n_in,
                              void* d_out, int out_size) {
    const float* x  = (const float*)d_in[0];
    const int*   ei = (const int*)d_in[1];
    const float* wl = (const float*)d_in[2];
    const float* bl = (const float*)d_in[3];
    const float* wr = (const float*)d_in[4];
    const float* wp = (const float*)d_in[5];
    const float* bp = (const float*)d_in[6];
    const float* ws = (const float*)d_in[7];
    const float* bs = (const float*)d_in[8];
    float* out = (float*)d_out;

    cudaFuncSetAttribute(node_mma_kernel,
                         cudaFuncAttributeMaxDynamicSharedMemorySize, SMEM_DYN);

    init_kernel<<<14417, 256>>>(x, wl, wr);
    hist_kernel<<<(N_EDGES + 255) / 256, 256>>>(ei);
    scan_block_kernel<<<NBLK, 256>>>();
    scan_add_kernel<<<NBLK, 256>>>();
    scatter_kernel<<<(N_EDGES + 255) / 256, 256>>>(ei);
    gather_kernel<<<N_NODES / 8, 256>>>();

    node_mma_kernel<<<296, 256, SMEM_DYN>>>(wp, ws, bl);
    finish_kernel<<<(N_NODES + 255) / 256, 256>>>(bp, bs, out);
}